// round 5
// baseline (speedup 1.0000x reference)
#include <cuda_runtime.h>
#include <float.h>

#define SDIM 512
#define BDIM 8
#define KMAX 16
#define EMPTY_DIST 362.1f
#define NFUSED (16 * 16 * BDIM)   // 2048 fused blocks

// Device-global scratch (zero at module load; self-reset by last fused block
// each call so every graph replay starts from identical zero state).
__device__ float4   g_pts[BDIM][KMAX];   // (-2y, -2x, y*y+x*x, 0) per point
__device__ int      g_cnt[BDIM];
__device__ float    g_sum[BDIM];
__device__ unsigned g_maxb[BDIM];
__device__ float    g_grad;
__device__ unsigned g_done;

// ---------------------------------------------------------------------------
__global__ void find_points(const float* __restrict__ pt) {
    int b = blockIdx.y;
    const float4* p4 = (const float4*)(pt + (size_t)b * SDIM * SDIM);
    const int n4 = SDIM * SDIM / 4;
    int stride = blockDim.x * gridDim.x;
    for (int c = blockIdx.x * blockDim.x + threadIdx.x; c < n4; c += stride) {
        float4 v = p4[c];
        float vv[4] = {v.x, v.y, v.z, v.w};
        #pragma unroll
        for (int j = 0; j < 4; j++) {
            if (vv[j] != 0.0f) {
                int slot = atomicAdd(&g_cnt[b], 1);
                if (slot < KMAX) {
                    int pix = c * 4 + j;
                    float y = (float)(pix >> 9);
                    float x = (float)(pix & 511);
                    g_pts[b][slot] = make_float4(-2.0f * y, -2.0f * x,
                                                 fmaf(y, y, x * x), 0.0f);
                }
            }
        }
    }
}

// ---------------------------------------------------------------------------
__device__ __forceinline__ float warp_sum(float v) {
    #pragma unroll
    for (int o = 16; o > 0; o >>= 1) v += __shfl_xor_sync(0xffffffffu, v, o);
    return v;
}
__device__ __forceinline__ float warp_max(float v) {
    #pragma unroll
    for (int o = 16; o > 0; o >>= 1) v = fmaxf(v, __shfl_xor_sync(0xffffffffu, v, o));
    return v;
}

// Fused kernel. Block=(32,8); tile 32x32; thread (tx,ty) owns 4 CONSECUTIVE
// rows 4*ty..4*ty+3 of column tx. Warp 0 additionally prunes distance planes
// to the tile's lower envelope (corner-dominance test) before the pixel loop.
__global__ __launch_bounds__(256) void fused_kernel(
    const float* __restrict__ pred,
    const float* __restrict__ ori,
    float* __restrict__ out)
{
    __shared__ float  img[34][35];
    __shared__ float4 spts[KMAX];     // surviving (pruned) planes, compacted
    __shared__ float  corn[KMAX][4];  // plane values at tile corners
    __shared__ int    scnt_s;         // number of survivors
    __shared__ float  red_s[8], red_m[8], red_g[8];

    int tx  = threadIdx.x, ty = threadIdx.y;
    int b   = blockIdx.z;
    int tx0 = blockIdx.x * 32;
    int ty0 = blockIdx.y * 32;
    int tid = ty * 32 + tx;

    const float* pb = pred + (size_t)b * SDIM * SDIM;
    const float* ob = ori  + (size_t)b * SDIM * SDIM;

    int cnt = min(g_cnt[b], KMAX);

    int x  = tx0 + tx;
    int y0 = ty0 + 4 * ty;

    // Interior: each thread loads its own 4 pixels of pred & ori, stores the
    // product, keeps pred in registers.
    float predv[4];
    #pragma unroll
    for (int r = 0; r < 4; r++) {
        int idx = (y0 + r) * SDIM + x;
        float p = pb[idx];
        predv[r] = p;
        img[4 * ty + 1 + r][tx + 1] = p * ob[idx];
    }

    // Perimeter halo: 132 elements, threads 0..131, no divisions.
    if (tid < 132) {
        int ly, lx;
        if      (tid < 34)  { ly = 0;             lx = tid;       }
        else if (tid < 68)  { ly = 33;            lx = tid - 34;  }
        else if (tid < 100) { ly = tid - 68 + 1;  lx = 0;         }
        else                { ly = tid - 100 + 1; lx = 33;        }
        int gy = ty0 - 1 + ly, gx = tx0 - 1 + lx;
        float v = 0.0f;
        if (gy >= 0 && gy < SDIM && gx >= 0 && gx < SDIM) {
            int idx = gy * SDIM + gx;
            v = pb[idx] * ob[idx];
        }
        img[ly][lx] = v;
    }

    // ---- Plane pruning (warp 0): plane k is dropped for this tile if some
    // plane j is <= it at all 4 tile corners (linear => <= everywhere in tile).
    if (tid < 32) {
        int k = tid;
        bool valid = (k < cnt);
        float4 p = make_float4(0.f, 0.f, 0.f, 0.f);
        float c0 = 0.f, c1 = 0.f, c2 = 0.f, c3 = 0.f;
        if (valid) {
            p = g_pts[b][k];
            float fxa = (float)tx0, fxb = (float)(tx0 + 31);
            float fya = (float)ty0, fyb = (float)(ty0 + 31);
            float a0 = fmaf(p.x, fya, p.z);
            float a1 = fmaf(p.x, fyb, p.z);
            c0 = fmaf(p.y, fxa, a0);
            c1 = fmaf(p.y, fxb, a0);
            c2 = fmaf(p.y, fxa, a1);
            c3 = fmaf(p.y, fxb, a1);
            corn[k][0] = c0; corn[k][1] = c1; corn[k][2] = c2; corn[k][3] = c3;
        }
        __syncwarp();
        bool keep = valid;
        if (valid) {
            for (int j = 0; j < cnt; j++) {
                if (j == k) continue;
                float d0 = corn[j][0], d1 = corn[j][1];
                float d2 = corn[j][2], d3 = corn[j][3];
                bool le = (d0 <= c0) && (d1 <= c1) && (d2 <= c2) && (d3 <= c3);
                bool st = (d0 <  c0) || (d1 <  c1) || (d2 <  c2) || (d3 <  c3);
                if (le && (st || j < k)) { keep = false; break; }
            }
        }
        unsigned m = __ballot_sync(0xffffffffu, keep);
        if (keep) {
            int slot = __popc(m & ((1u << k) - 1u));
            spts[slot] = p;
        }
        if (tid == 0) scnt_s = __popc(m);
    }

    // ---- distance setup: min_k d^2 = (fy^2+fx^2) + min_k t_k
    float fx  = (float)x;
    float fx2 = fx * fx;
    float fyr[4], tmin[4];
    #pragma unroll
    for (int r = 0; r < 4; r++) {
        fyr[r]  = (float)(y0 + r);
        tmin[r] = FLT_MAX;
    }

    __syncthreads();

    int sc = scnt_s;
    for (int k = 0; k < sc; k++) {
        float4 p = spts[k];
        float pk = fmaf(p.y, fx, p.z);
        #pragma unroll
        for (int r = 0; r < 4; r++)
            tmin[r] = fminf(tmin[r], fmaf(p.x, fyr[r], pk));
    }

    float lsum = 0.0f, lmax = 0.0f, lgrad = 0.0f;

    // Rolling 3x3 window over 4 consecutive rows: 3 new LDS per row.
    int lx = tx + 1;
    float t0 = img[4 * ty + 0][lx - 1], t1 = img[4 * ty + 0][lx], t2 = img[4 * ty + 0][lx + 1];
    float m0 = img[4 * ty + 1][lx - 1], m1 = img[4 * ty + 1][lx], m2 = img[4 * ty + 1][lx + 1];

    bool x_in = (x >= 1) && (x <= SDIM - 2);

    #pragma unroll
    for (int r = 0; r < 4; r++) {
        int y  = y0 + r;
        int ly = 4 * ty + 2 + r;
        float b0 = img[ly][lx - 1], b1 = img[ly][lx], b2 = img[ly][lx + 1];

        // distance term
        float dd;
        if (cnt > 0) {
            float d2 = fmaxf(fmaf(fyr[r], fyr[r], fx2) + tmin[r], 0.0f);
            dd = fmaxf(sqrtf(d2) - 1.0f, 0.0f);   // distance_thre = 1
        } else {
            dd = EMPTY_DIST - 1.0f;
        }
        lmax = fmaxf(lmax, dd);
        lsum = fmaf(predv[r], dd, lsum);

        // gradient term: u=b-h, v=f-d, w=a-i, z=c-g
        float u = t1 - b1;
        float v = m2 - m0;
        float w = t0 - b2;
        float z = t2 - b0;
        float f0 = fmaf(2.0f, v, z - w);
        float f1 = fmaf(2.0f, u, z + w);
        float f2 = fmaf(2.0f, w, u - v);
        float f3 = fmaf(2.0f, z, u + v);
        float m4 = fmaxf(fmaxf(fabsf(f0), fabsf(f1)),
                         fmaxf(fabsf(f2), fabsf(f3)));
        bool in = x_in && (y >= 1) && (y <= SDIM - 2);
        lgrad += in ? m4 : 0.0f;

        // roll window
        t0 = m0; t1 = m1; t2 = m2;
        m0 = b0; m1 = b1; m2 = b2;
    }

    // Block reduction -> one atomic set per block
    float ws = warp_sum(lsum);
    float wm = warp_max(lmax);
    float wg = warp_sum(lgrad);
    int warp = tid >> 5, lane = tid & 31;
    if (lane == 0) { red_s[warp] = ws; red_m[warp] = wm; red_g[warp] = wg; }
    __syncthreads();

    if (tid == 0) {
        float bs = 0.0f, bm = 0.0f, bg = 0.0f;
        #pragma unroll
        for (int w2 = 0; w2 < 8; w2++) {
            bs += red_s[w2];
            bm = fmaxf(bm, red_m[w2]);
            bg += red_g[w2];
        }
        atomicAdd(&g_sum[b], bs);
        atomicMax(&g_maxb[b], __float_as_uint(bm));
        atomicAdd(&g_grad, bg);

        __threadfence();
        unsigned ticket = atomicAdd(&g_done, 1u);
        if (ticket == NFUSED - 1) {
            float dl = 0.0f;
            #pragma unroll
            for (int i = 0; i < BDIM; i++) {
                float s = atomicAdd(&g_sum[i], 0.0f);
                float m = __uint_as_float(atomicMax(&g_maxb[i], 0u));
                dl += s / m;
            }
            float gr = atomicAdd(&g_grad, 0.0f);
            float denom = (float)SDIM * (float)SDIM * (float)BDIM;
            out[0] = dl / denom;
            out[1] = gr / denom;

            #pragma unroll
            for (int i = 0; i < BDIM; i++) {
                g_cnt[i]  = 0;
                g_sum[i]  = 0.0f;
                g_maxb[i] = 0u;
            }
            g_grad = 0.0f;
            __threadfence();
            g_done = 0u;
        }
    }
}

extern "C" void kernel_launch(void* const* d_in, const int* in_sizes, int n_in,
                              void* d_out, int out_size) {
    const float* pred = (const float*)d_in[0];
    const float* ptl  = (const float*)d_in[1];
    const float* ori  = (const float*)d_in[2];
    float* out = (float*)d_out;

    find_points<<<dim3(64, BDIM), 256>>>(ptl);
    fused_kernel<<<dim3(SDIM / 32, SDIM / 32, BDIM), dim3(32, 8)>>>(pred, ori, out);
}